// round 2
// baseline (speedup 1.0000x reference)
#include <cuda_runtime.h>
#include <math.h>

#define NS 512
#define DD 400
#define HH 400

// ---- scratch (no allocations allowed) ----
__device__ float g_hxT[HH * NS];   // transposed: [h][sample]
__device__ float g_hyT[HH * NS];   // transposed, b1 folded in
__device__ float g_expsum[NS];     // per-row sum of exp(T1) = sum(1+e^v)
__device__ float g_tsum;           // sum of all T1
__device__ float g_dsum;           // sum of diagonal T1 (== T0 sum)
__device__ int   g_cnt = 0;

// ---- packed f32x2 helpers (sm_10x) ----
#define PACK2(d, lo, hi) \
    asm("mov.b64 %0, {%1,%2};" : "=l"(d) : "f"(lo), "f"(hi))
#define FMA2(acc, a, b) \
    asm("fma.rn.f32x2 %0, %1, %2, %0;" : "+l"(acc) : "l"(a), "l"(b))
// acc2 += relu(y2 + x2) * w2   (componentwise)
#define RELU_FMA2(acc, y2, x2, w2)                      \
    asm("{\n\t"                                         \
        ".reg .b64 t;\n\t"                              \
        ".reg .f32 lo, hi;\n\t"                         \
        "add.rn.f32x2 t, %1, %2;\n\t"                   \
        "mov.b64 {lo, hi}, t;\n\t"                      \
        "max.f32 lo, lo, 0f00000000;\n\t"               \
        "max.f32 hi, hi, 0f00000000;\n\t"               \
        "mov.b64 t, {lo, hi};\n\t"                      \
        "fma.rn.f32x2 %0, t, %3, %0;\n\t"               \
        "}" : "+l"(acc) : "l"(y2), "l"(x2), "l"(w2))

// ======================================================================
// Kernel 1: dual GEMM, transposed output.
//   z=0: g_hxT[h][m] = sum_k x[m,k] W1[h,k]
//   z=1: g_hyT[h][m] = sum_k y[m,k] W1[h,400+k] + b1[h]
// 64(m) x 64(h) tiles, BK=16, 256 threads, 4h x 4m register tiles, FFMA2.
// Block (0,0,0) also zeroes the pair-kernel accumulators.
// ======================================================================
__global__ void gemm_h_kernel(const float* __restrict__ x,
                              const float* __restrict__ y,
                              const float* __restrict__ W1,
                              const float* __restrict__ b1) {
    const int z = blockIdx.z;

    if (z == 0 && blockIdx.x == 0 && blockIdx.y == 0) {
        for (int r = threadIdx.x; r < NS; r += 256) g_expsum[r] = 0.f;
        if (threadIdx.x == 0) { g_tsum = 0.f; g_dsum = 0.f; g_cnt = 0; }
    }

    const float* A   = z ? y : x;
    const int   woff = z ? DD : 0;
    float*      outT = z ? g_hyT : g_hxT;

    const int m0 = blockIdx.x * 64;   // sample dim
    const int h0 = blockIdx.y * 64;   // hidden dim (up to 400)

    __shared__ __align__(16) float As[16][66];   // [k][m]
    __shared__ __align__(16) float Hs[16][66];   // [k][h]

    const int tid = threadIdx.x;      // 256
    const int tx  = tid & 15;         // m group (4 m each)
    const int ty  = tid >> 4;         // h group (4 h each)

    unsigned long long acc[4][2] = {};   // [ih][m-pair], zero bits = 0.0f

    for (int k0 = 0; k0 < DD; k0 += 16) {
        {
            int r  = tid >> 2;            // 0..63
            int kq = (tid & 3) * 4;       // 0,4,8,12
            float4 v = *reinterpret_cast<const float4*>(&A[(m0 + r) * DD + k0 + kq]);
            As[kq + 0][r] = v.x; As[kq + 1][r] = v.y;
            As[kq + 2][r] = v.z; As[kq + 3][r] = v.w;

            float4 w = make_float4(0.f, 0.f, 0.f, 0.f);
            if (h0 + r < HH)
                w = *reinterpret_cast<const float4*>(&W1[(h0 + r) * (2 * DD) + woff + k0 + kq]);
            Hs[kq + 0][r] = w.x; Hs[kq + 1][r] = w.y;
            Hs[kq + 2][r] = w.z; Hs[kq + 3][r] = w.w;
        }
        __syncthreads();

        #pragma unroll
        for (int kk = 0; kk < 16; kk++) {
            unsigned long long m2a =
                *reinterpret_cast<const unsigned long long*>(&As[kk][tx * 4]);
            unsigned long long m2b =
                *reinterpret_cast<const unsigned long long*>(&As[kk][tx * 4 + 2]);
            #pragma unroll
            for (int ih = 0; ih < 4; ih++) {
                float hv = Hs[kk][ty * 4 + ih];
                unsigned long long h2; PACK2(h2, hv, hv);
                FMA2(acc[ih][0], h2, m2a);
                FMA2(acc[ih][1], h2, m2b);
            }
        }
        __syncthreads();
    }

    #pragma unroll
    for (int ih = 0; ih < 4; ih++) {
        int h = h0 + ty * 4 + ih;
        if (h < HH) {
            float2 p0 = *reinterpret_cast<float2*>(&acc[ih][0]);
            float2 p1 = *reinterpret_cast<float2*>(&acc[ih][1]);
            if (z) {
                float b = b1[h];
                p0.x += b; p0.y += b; p1.x += b; p1.y += b;
            }
            float4 v = make_float4(p0.x, p0.y, p1.x, p1.y);
            *reinterpret_cast<float4*>(&outT[h * NS + m0 + tx * 4]) = v;
        }
    }
}

// ======================================================================
// Kernel 2: pair relu-dot + fused epilogue + last-block finalize.
//   v[i,j] = sum_h relu(g_hyT[h][i] + g_hxT[h][j]) * W2[h] + b2
//   T1    = softplus(v);  exp(T1) = 1 + e^v
// Tile 32(i) x 64(j), 256 threads, 1 i x 8 j (4 packed pairs) per thread.
// Grid (8, 16) = 128 blocks.
// ======================================================================
__global__ void pair_kernel(const float* __restrict__ W2,
                            const float* __restrict__ b2p,
                            float* __restrict__ out) {
    const int j0  = blockIdx.x * 64;
    const int i0  = blockIdx.y * 32;
    const int tid = threadIdx.x;    // 256
    const int tx  = tid & 7;        // j group (8 j each)
    const int iy  = tid >> 3;       // i row (0..31)

    __shared__ __align__(16) float Ys[16][32];
    __shared__ __align__(16) float Xs[16][64];
    __shared__ unsigned long long Wp[16];

    unsigned long long acc[4] = {};

    for (int k0 = 0; k0 < HH; k0 += 16) {
        {
            int a = tid;
            Ys[a >> 5][a & 31] = g_hyT[(k0 + (a >> 5)) * NS + i0 + (a & 31)];
            a = tid + 256;
            Ys[a >> 5][a & 31] = g_hyT[(k0 + (a >> 5)) * NS + i0 + (a & 31)];
            #pragma unroll
            for (int it = 0; it < 4; it++) {
                int b = tid + it * 256;
                Xs[b >> 6][b & 63] = g_hxT[(k0 + (b >> 6)) * NS + j0 + (b & 63)];
            }
            if (tid < 16) {
                float w = W2[k0 + tid];
                unsigned long long w2; PACK2(w2, w, w);
                Wp[tid] = w2;
            }
        }
        __syncthreads();

        #pragma unroll
        for (int kk = 0; kk < 16; kk++) {
            float yv = Ys[kk][iy];
            unsigned long long y2; PACK2(y2, yv, yv);
            unsigned long long w2 = Wp[kk];
            #pragma unroll
            for (int p = 0; p < 4; p++) {
                unsigned long long x2 =
                    *reinterpret_cast<const unsigned long long*>(&Xs[kk][tx * 8 + 2 * p]);
                RELU_FMA2(acc[p], y2, x2, w2);
            }
        }
        __syncthreads();
    }

    // ---- fused epilogue ----
    const float b2 = b2p[0];
    const int   i  = i0 + iy;
    float eSum = 0.f, tSum = 0.f, dSum = 0.f;
    #pragma unroll
    for (int p = 0; p < 4; p++) {
        float2 s2 = *reinterpret_cast<float2*>(&acc[p]);
        #pragma unroll
        for (int q = 0; q < 2; q++) {
            float v = (q ? s2.y : s2.x) + b2;
            float t = fmaxf(v, 0.f) + __logf(1.f + __expf(-fabsf(v)));
            eSum += 1.f + __expf(v);        // exp(softplus(v)) == 1 + e^v
            tSum += t;
            int j = j0 + tx * 8 + p * 2 + q;
            if (j == i) dSum += t;
        }
    }

    // per-row sum of exp over the 8 tx lanes of this row
    #pragma unroll
    for (int o = 4; o; o >>= 1)
        eSum += __shfl_down_sync(0xffffffffu, eSum, o, 8);
    if (tx == 0) atomicAdd(&g_expsum[i], eSum);

    // block totals
    #pragma unroll
    for (int o = 16; o; o >>= 1) {
        tSum += __shfl_down_sync(0xffffffffu, tSum, o);
        dSum += __shfl_down_sync(0xffffffffu, dSum, o);
    }
    __shared__ float wsum[8], wdia[8];
    const int wid = tid >> 5, lane = tid & 31;
    if (lane == 0) { wsum[wid] = tSum; wdia[wid] = dSum; }
    __syncthreads();
    if (tid == 0) {
        float ts = 0.f, ds = 0.f;
        #pragma unroll
        for (int w = 0; w < 8; w++) { ts += wsum[w]; ds += wdia[w]; }
        atomicAdd(&g_tsum, ts);
        atomicAdd(&g_dsum, ds);
    }

    // ---- last block finalizes ----
    __threadfence();
    __shared__ int ticket;
    if (tid == 0) ticket = atomicAdd(&g_cnt, 1);
    __syncthreads();
    if (ticket == 8 * 16 - 1) {
        float ls = __logf(g_expsum[tid]) + __logf(g_expsum[tid + 256]);
        #pragma unroll
        for (int o = 16; o; o >>= 1)
            ls += __shfl_down_sync(0xffffffffu, ls, o);
        __shared__ float lw[8];
        if (lane == 0) lw[wid] = ls;
        __syncthreads();
        if (tid == 0) {
            float lsum = 0.f;
            #pragma unroll
            for (int w = 0; w < 8; w++) lsum += lw[w];
            const float n = (float)NS;
            float t0_mean = g_dsum / n;
            out[0] = t0_mean - (lsum / n - logf(n));   // lower bound
            out[1] = t0_mean - g_tsum / (n * n);       // upper bound
            g_cnt = 0;
        }
    }
}

// ======================================================================
extern "C" void kernel_launch(void* const* d_in, const int* in_sizes, int n_in,
                              void* d_out, int out_size) {
    const float* x  = (const float*)d_in[0];
    const float* y  = (const float*)d_in[1];
    const float* W1 = (const float*)d_in[2];
    const float* b1 = (const float*)d_in[3];
    const float* W2 = (const float*)d_in[4];
    const float* b2 = (const float*)d_in[5];
    float* out = (float*)d_out;

    dim3 ggrid(NS / 64, (HH + 63) / 64, 2);   // (8, 7, 2)
    gemm_h_kernel<<<ggrid, 256>>>(x, y, W1, b1);

    dim3 pgrid(NS / 64, NS / 32);             // (8, 16) = 128 blocks
    pair_kernel<<<pgrid, 256>>>(W2, b2, out);
}

// round 3
// speedup vs baseline: 1.2451x; 1.2451x over previous
#include <cuda_runtime.h>
#include <math.h>

#define NS 512
#define DD 400
#define HH 400

// ---- scratch (no allocations allowed) ----
__device__ float g_hxT[HH * NS];   // transposed: [h][sample]
__device__ float g_hyT[HH * NS];   // transposed, b1 folded in
__device__ float g_expsum[NS];     // per-row sum of exp(T1) = 1 + e^v
__device__ float g_tsum;           // sum of all T1
__device__ float g_dsum;           // sum of diag T1 (== T0 sum)
__device__ int   g_cnt = 0;

// ---- packed f32x2 helpers (sm_10x) ----
#define PACK2(d, lo, hi) \
    asm("mov.b64 %0, {%1,%2};" : "=l"(d) : "f"(lo), "f"(hi))
#define FMA2(acc, a, b) \
    asm("fma.rn.f32x2 %0, %1, %2, %0;" : "+l"(acc) : "l"(a), "l"(b))
// acc2 += relu(y2 + x2) * w2   (componentwise)
#define RELU_FMA2(acc, y2, x2, w2)                      \
    asm("{\n\t"                                         \
        ".reg .b64 t;\n\t"                              \
        ".reg .f32 lo, hi;\n\t"                         \
        "add.rn.f32x2 t, %1, %2;\n\t"                   \
        "mov.b64 {lo, hi}, t;\n\t"                      \
        "max.f32 lo, lo, 0f00000000;\n\t"               \
        "max.f32 hi, hi, 0f00000000;\n\t"               \
        "mov.b64 t, {lo, hi};\n\t"                      \
        "fma.rn.f32x2 %0, t, %3, %0;\n\t"               \
        "}" : "+l"(acc) : "l"(y2), "l"(x2), "l"(w2))

// ======================================================================
// Kernel 1: dual GEMM, transposed output.
//   z=0: g_hxT[h][m] = sum_k x[m,k] W1[h,k]
//   z=1: g_hyT[h][m] = sum_k y[m,k] W1[h,400+k] + b1[h]
// Tile 32h x 128m, BK=16, 128 threads, thread tile 4h x 8m (FFMA2).
// Grid (4 m, 13 h, 2 z) = 104 blocks. Prefetch-to-regs pipelining.
// ======================================================================
__global__ void __launch_bounds__(128)
gemm_h_kernel(const float* __restrict__ x,
              const float* __restrict__ y,
              const float* __restrict__ W1,
              const float* __restrict__ b1) {
    const int z = blockIdx.z;

    if (z == 0 && blockIdx.x == 0 && blockIdx.y == 0) {
        for (int r = threadIdx.x; r < NS; r += 128) g_expsum[r] = 0.f;
        if (threadIdx.x == 0) { g_tsum = 0.f; g_dsum = 0.f; g_cnt = 0; }
    }

    const float* A   = z ? y : x;
    const int   woff = z ? DD : 0;
    float*      outT = z ? g_hyT : g_hxT;

    const int m0 = blockIdx.x * 128;
    const int h0 = blockIdx.y * 32;

    __shared__ __align__(16) float As[16][128];  // [k][m]
    __shared__ __align__(16) float Hs[16][32];   // [k][h]

    const int tid = threadIdx.x;       // 128
    const int tx  = tid & 15;          // m group: 8 m each
    const int ty  = tid >> 4;          // h group: 4 h each (0..7)

    // staging regs
    float4 a_r[4];   // 4 k-quads of row m=tid
    float4 h_r;      // 1 k-quad of row h=(tid&31), quad (tid>>5)

    const int hs_h  = tid & 31;
    const int hs_kq = (tid >> 5) * 4;
    const bool h_ok = (h0 + hs_h) < HH;

    // ---- load tile 0 ----
    #pragma unroll
    for (int it = 0; it < 4; it++)
        a_r[it] = *reinterpret_cast<const float4*>(&A[(m0 + tid) * DD + it * 4]);
    h_r = make_float4(0.f, 0.f, 0.f, 0.f);
    if (h_ok)
        h_r = *reinterpret_cast<const float4*>(&W1[(h0 + hs_h) * (2 * DD) + woff + hs_kq]);

    unsigned long long acc[4][4] = {};   // [ih][m-pair]

    for (int t = 0; t < DD / 16; t++) {
        // store staged regs to shared
        #pragma unroll
        for (int it = 0; it < 4; it++) {
            As[it * 4 + 0][tid] = a_r[it].x;
            As[it * 4 + 1][tid] = a_r[it].y;
            As[it * 4 + 2][tid] = a_r[it].z;
            As[it * 4 + 3][tid] = a_r[it].w;
        }
        Hs[hs_kq + 0][hs_h] = h_r.x;
        Hs[hs_kq + 1][hs_h] = h_r.y;
        Hs[hs_kq + 2][hs_h] = h_r.z;
        Hs[hs_kq + 3][hs_h] = h_r.w;
        __syncthreads();

        // prefetch tile t+1
        if (t + 1 < DD / 16) {
            int k0 = (t + 1) * 16;
            #pragma unroll
            for (int it = 0; it < 4; it++)
                a_r[it] = *reinterpret_cast<const float4*>(&A[(m0 + tid) * DD + k0 + it * 4]);
            if (h_ok)
                h_r = *reinterpret_cast<const float4*>(&W1[(h0 + hs_h) * (2 * DD) + woff + k0 + hs_kq]);
        }

        // compute on tile t
        #pragma unroll
        for (int kk = 0; kk < 16; kk++) {
            float4 hv = *reinterpret_cast<const float4*>(&Hs[kk][ty * 4]);
            unsigned long long m01 = *reinterpret_cast<const unsigned long long*>(&As[kk][tx * 8 + 0]);
            unsigned long long m23 = *reinterpret_cast<const unsigned long long*>(&As[kk][tx * 8 + 2]);
            unsigned long long m45 = *reinterpret_cast<const unsigned long long*>(&As[kk][tx * 8 + 4]);
            unsigned long long m67 = *reinterpret_cast<const unsigned long long*>(&As[kk][tx * 8 + 6]);
            unsigned long long h2;
            PACK2(h2, hv.x, hv.x);
            FMA2(acc[0][0], h2, m01); FMA2(acc[0][1], h2, m23);
            FMA2(acc[0][2], h2, m45); FMA2(acc[0][3], h2, m67);
            PACK2(h2, hv.y, hv.y);
            FMA2(acc[1][0], h2, m01); FMA2(acc[1][1], h2, m23);
            FMA2(acc[1][2], h2, m45); FMA2(acc[1][3], h2, m67);
            PACK2(h2, hv.z, hv.z);
            FMA2(acc[2][0], h2, m01); FMA2(acc[2][1], h2, m23);
            FMA2(acc[2][2], h2, m45); FMA2(acc[2][3], h2, m67);
            PACK2(h2, hv.w, hv.w);
            FMA2(acc[3][0], h2, m01); FMA2(acc[3][1], h2, m23);
            FMA2(acc[3][2], h2, m45); FMA2(acc[3][3], h2, m67);
        }
        __syncthreads();
    }

    #pragma unroll
    for (int ih = 0; ih < 4; ih++) {
        int h = h0 + ty * 4 + ih;
        if (h < HH) {
            float2 p0 = *reinterpret_cast<float2*>(&acc[ih][0]);
            float2 p1 = *reinterpret_cast<float2*>(&acc[ih][1]);
            float2 p2 = *reinterpret_cast<float2*>(&acc[ih][2]);
            float2 p3 = *reinterpret_cast<float2*>(&acc[ih][3]);
            if (z) {
                float b = b1[h];
                p0.x += b; p0.y += b; p1.x += b; p1.y += b;
                p2.x += b; p2.y += b; p3.x += b; p3.y += b;
            }
            float* o = &outT[h * NS + m0 + tx * 8];
            *reinterpret_cast<float4*>(o + 0) = make_float4(p0.x, p0.y, p1.x, p1.y);
            *reinterpret_cast<float4*>(o + 4) = make_float4(p2.x, p2.y, p3.x, p3.y);
        }
    }
}

// ======================================================================
// Kernel 2: pair relu-dot + fused epilogue + last-block finalize.
//   v[i,j] = sum_h relu(g_hyT[h][i] + g_hxT[h][j]) * W2[h] + b2
// Tile 32i x 64j, 128 threads, thread tile 4i x 4j. Grid (8, 16) = 128.
// ======================================================================
__global__ void __launch_bounds__(128)
pair_kernel(const float* __restrict__ W2,
            const float* __restrict__ b2p,
            float* __restrict__ out) {
    const int j0  = blockIdx.x * 64;
    const int i0  = blockIdx.y * 32;
    const int tid = threadIdx.x;    // 128
    const int tx  = tid & 15;       // j group: 4 j each
    const int ty  = tid >> 4;       // i group: 4 i each (0..7)

    __shared__ __align__(16) float Ys[16][32];
    __shared__ __align__(16) float Xs[16][64];
    __shared__ __align__(16) unsigned long long Wp[16];

    // staging regs
    float ys_r[4], xs_r[8], w_r = 0.f;

    // ---- load tile 0 ----
    #pragma unroll
    for (int it = 0; it < 4; it++) {
        int a = tid + it * 128;
        ys_r[it] = g_hyT[(a >> 5) * NS + i0 + (a & 31)];
    }
    #pragma unroll
    for (int it = 0; it < 8; it++) {
        int a = tid + it * 128;
        xs_r[it] = g_hxT[(a >> 6) * NS + j0 + (a & 63)];
    }
    if (tid < 16) w_r = W2[tid];

    unsigned long long acc[4][2] = {};   // [ii][j-pair]

    for (int t = 0; t < HH / 16; t++) {
        // store staged regs
        #pragma unroll
        for (int it = 0; it < 4; it++) {
            int a = tid + it * 128;
            Ys[a >> 5][a & 31] = ys_r[it];
        }
        #pragma unroll
        for (int it = 0; it < 8; it++) {
            int a = tid + it * 128;
            Xs[a >> 6][a & 63] = xs_r[it];
        }
        if (tid < 16) {
            unsigned long long w2;
            PACK2(w2, w_r, w_r);
            Wp[tid] = w2;
        }
        __syncthreads();

        // prefetch tile t+1
        if (t + 1 < HH / 16) {
            int k0 = (t + 1) * 16;
            #pragma unroll
            for (int it = 0; it < 4; it++) {
                int a = tid + it * 128;
                ys_r[it] = g_hyT[(k0 + (a >> 5)) * NS + i0 + (a & 31)];
            }
            #pragma unroll
            for (int it = 0; it < 8; it++) {
                int a = tid + it * 128;
                xs_r[it] = g_hxT[(k0 + (a >> 6)) * NS + j0 + (a & 63)];
            }
            if (tid < 16) w_r = W2[k0 + tid];
        }

        // compute on tile t
        #pragma unroll
        for (int kk = 0; kk < 16; kk++) {
            float4 y4 = *reinterpret_cast<const float4*>(&Ys[kk][ty * 4]);
            unsigned long long x01 = *reinterpret_cast<const unsigned long long*>(&Xs[kk][tx * 4 + 0]);
            unsigned long long x23 = *reinterpret_cast<const unsigned long long*>(&Xs[kk][tx * 4 + 2]);
            unsigned long long w2 = Wp[kk];
            unsigned long long y2;
            PACK2(y2, y4.x, y4.x);
            RELU_FMA2(acc[0][0], y2, x01, w2); RELU_FMA2(acc[0][1], y2, x23, w2);
            PACK2(y2, y4.y, y4.y);
            RELU_FMA2(acc[1][0], y2, x01, w2); RELU_FMA2(acc[1][1], y2, x23, w2);
            PACK2(y2, y4.z, y4.z);
            RELU_FMA2(acc[2][0], y2, x01, w2); RELU_FMA2(acc[2][1], y2, x23, w2);
            PACK2(y2, y4.w, y4.w);
            RELU_FMA2(acc[3][0], y2, x01, w2); RELU_FMA2(acc[3][1], y2, x23, w2);
        }
        __syncthreads();
    }

    // ---- fused epilogue (accurate math: rel-err budget matters) ----
    const float b2 = b2p[0];
    float tSum = 0.f, dSum = 0.f;

    #pragma unroll
    for (int ii = 0; ii < 4; ii++) {
        const int i = i0 + ty * 4 + ii;
        float2 p01 = *reinterpret_cast<float2*>(&acc[ii][0]);
        float2 p23 = *reinterpret_cast<float2*>(&acc[ii][1]);
        float vq[4] = {p01.x, p01.y, p23.x, p23.y};
        float eRow = 0.f;
        #pragma unroll
        for (int q = 0; q < 4; q++) {
            float v = vq[q] + b2;
            float tt = fmaxf(v, 0.f) + log1pf(expf(-fabsf(v)));
            eRow += 1.f + expf(v);            // exp(softplus(v)) == 1 + e^v
            tSum += tt;
            if (j0 + tx * 4 + q == i) dSum += tt;
        }
        // reduce row partial over the 16 j-lanes (contiguous in the warp)
        #pragma unroll
        for (int o = 8; o; o >>= 1)
            eRow += __shfl_down_sync(0xffffffffu, eRow, o, 16);
        if (tx == 0) atomicAdd(&g_expsum[i], eRow);
    }

    // block totals
    const int wid = tid >> 5, lane = tid & 31;
    #pragma unroll
    for (int o = 16; o; o >>= 1) {
        tSum += __shfl_down_sync(0xffffffffu, tSum, o);
        dSum += __shfl_down_sync(0xffffffffu, dSum, o);
    }
    __shared__ float wsum[4], wdia[4];
    if (lane == 0) { wsum[wid] = tSum; wdia[wid] = dSum; }
    __syncthreads();
    if (tid == 0) {
        float ts = wsum[0] + wsum[1] + wsum[2] + wsum[3];
        float ds = wdia[0] + wdia[1] + wdia[2] + wdia[3];
        atomicAdd(&g_tsum, ts);
        atomicAdd(&g_dsum, ds);
    }

    // ---- last block finalizes ----
    __threadfence();
    __shared__ int ticket;
    if (tid == 0) ticket = atomicAdd(&g_cnt, 1);
    __syncthreads();
    if (ticket == 8 * 16 - 1) {
        float ls = 0.f;
        #pragma unroll
        for (int it = 0; it < 4; it++)
            ls += logf(g_expsum[tid + it * 128]);
        #pragma unroll
        for (int o = 16; o; o >>= 1)
            ls += __shfl_down_sync(0xffffffffu, ls, o);
        __shared__ float lw[4];
        if (lane == 0) lw[wid] = ls;
        __syncthreads();
        if (tid == 0) {
            float lsum = lw[0] + lw[1] + lw[2] + lw[3];
            const float n = (float)NS;
            float t0_mean = g_dsum / n;
            out[0] = t0_mean - (lsum / n - logf(n));   // lower bound
            out[1] = t0_mean - g_tsum / (n * n);       // upper bound
            g_cnt = 0;
        }
    }
}

// ======================================================================
extern "C" void kernel_launch(void* const* d_in, const int* in_sizes, int n_in,
                              void* d_out, int out_size) {
    const float* x  = (const float*)d_in[0];
    const float* y  = (const float*)d_in[1];
    const float* W1 = (const float*)d_in[2];
    const float* b1 = (const float*)d_in[3];
    const float* W2 = (const float*)d_in[4];
    const float* b2 = (const float*)d_in[5];
    float* out = (float*)d_out;

    dim3 ggrid(NS / 128, (HH + 31) / 32, 2);   // (4, 13, 2) = 104 blocks
    gemm_h_kernel<<<ggrid, 128>>>(x, y, W1, b1);

    dim3 pgrid(NS / 64, NS / 32);              // (8, 16) = 128 blocks
    pair_kernel<<<pgrid, 128>>>(W2, b2, out);
}